// round 3
// baseline (speedup 1.0000x reference)
#include <cuda_runtime.h>
#include <cuda_bf16.h>

#define D 8192
#define B 8

// Static device scratch (no runtime allocation allowed).
__device__ __align__(16) __nv_bfloat16 g_Mb[(size_t)D * (size_t)D];  // bf16 copy of M
__device__ __align__(16) float g_u[B * D];   // pre-normalization activations
__device__ __align__(16) float g_h[B * D];   // normalized state hs_t

// ---------------------------------------------------------------------------
// One-time fp32 -> bf16 conversion of M
// ---------------------------------------------------------------------------
__global__ void convert_kernel(const float* __restrict__ M) {
    size_t idx    = (size_t)blockIdx.x * blockDim.x + threadIdx.x;
    size_t stride = (size_t)gridDim.x * blockDim.x;
    size_t n4     = (size_t)D * (size_t)D / 4;
    const float4* in4 = reinterpret_cast<const float4*>(M);
    uint2* out4       = reinterpret_cast<uint2*>(g_Mb);
    for (size_t i = idx; i < n4; i += stride) {
        float4 v = in4[i];
        __nv_bfloat162 lo = __floats2bfloat162_rn(v.x, v.y);
        __nv_bfloat162 hi = __floats2bfloat162_rn(v.z, v.w);
        uint2 o;
        o.x = *reinterpret_cast<unsigned*>(&lo);
        o.y = *reinterpret_cast<unsigned*>(&hi);
        out4[i] = o;
    }
}

// ---------------------------------------------------------------------------
// One step's pre-activation:  u = leaky( 0.5*hs + h @ M )
//   FIRST step: h = x, hs = hs_in (the (1,D) zeros input, broadcast)
//   later:      h = hs = g_h (previous normalized state)
//
// Grid: 128 blocks x 512 threads. Block owns 64 output columns.
// Thread (lane, ks): lane = tid&31 = column-pair (2 adjacent cols via one
// 4B uint = 2 bf16), ks = tid>>5 = warp id = k-slice of 512 i-values.
// A warp therefore loads 64 consecutive bf16 = 128 contiguous bytes of M
// per row i (perfectly coalesced), and its h loads are warp-uniform.
// ---------------------------------------------------------------------------
template <bool FIRST>
__global__ void __launch_bounds__(512, 1)
iter_kernel(const float* __restrict__ x, const float* __restrict__ hs_in) {
    const int tid  = threadIdx.x;
    const int lane = tid & 31;      // column pair within the block's 64 cols
    const int ks   = tid >> 5;      // warp id = k-slice 0..15
    const int j0   = blockIdx.x * 64;

    const float* __restrict__ h = FIRST ? x : g_h;

    float acc[B][2];
#pragma unroll
    for (int b = 0; b < B; b++) { acc[b][0] = 0.f; acc[b][1] = 0.f; }

    const unsigned* __restrict__ M2 = reinterpret_cast<const unsigned*>(g_Mb);

    const int iBeg = ks * 512;
#pragma unroll 1
    for (int ii = 0; ii < 512; ii += 4) {
        const int i = iBeg + ii;
        // batch loads up front for MLP
        float4 hv[B];
#pragma unroll
        for (int b = 0; b < B; b++)
            hv[b] = *reinterpret_cast<const float4*>(&h[b * D + i]);
        unsigned mv[4];
#pragma unroll
        for (int t = 0; t < 4; t++)
            mv[t] = M2[((size_t)(i + t) * D + (size_t)j0) / 2 + lane];

#pragma unroll
        for (int t = 0; t < 4; t++) {
            __nv_bfloat162 mb = *reinterpret_cast<__nv_bfloat162*>(&mv[t]);
            const float m0 = __low2float(mb);   // column j0 + 2*lane
            const float m1 = __high2float(mb);  // column j0 + 2*lane + 1
#pragma unroll
            for (int b = 0; b < B; b++) {
                const float hb = (t == 0) ? hv[b].x : (t == 1) ? hv[b].y
                                          : (t == 2) ? hv[b].z : hv[b].w;
                acc[b][0] = fmaf(hb, m0, acc[b][0]);
                acc[b][1] = fmaf(hb, m1, acc[b][1]);
            }
        }
    }

    // Flat reduction over the 16 k-slices.
    // smem[(ks*8 + b)*64 + col], col = local column 0..63.
    __shared__ float smem[16 * 8 * 64];
#pragma unroll
    for (int b = 0; b < B; b++) {
        smem[(ks * 8 + b) * 64 + 2 * lane + 0] = acc[b][0];
        smem[(ks * 8 + b) * 64 + 2 * lane + 1] = acc[b][1];
    }
    __syncthreads();

    // 512 outputs = 8 batches x 64 cols; one per thread.
    {
        const int col = tid & 63;
        const int b   = tid >> 6;
        float s = 0.f;
#pragma unroll
        for (int k2 = 0; k2 < 16; k2++) s += smem[(k2 * 8 + b) * 64 + col];

        const int j = j0 + col;
        const float dec = FIRST ? hs_in[j] : g_h[b * D + j];
        float val = fmaf(0.5f, dec, s);
        val = (val >= 0.f) ? val : 0.01f * val;   // leaky_relu
        g_u[b * D + j] = val;
    }
}

// ---------------------------------------------------------------------------
// Row-wise L2 normalize: dst[b] = u[b] / max(||u[b]||, 1e-12)
// dst is resolved IN DEVICE CODE: g_h for intermediate steps (to_ext == 0),
// the harness output buffer for the final step (to_ext == 1).
// NOTE: never pass a __device__ symbol as a host-side kernel argument —
// that silently passes the host shadow address (root cause of R2 failure).
// ---------------------------------------------------------------------------
__global__ void norm_kernel(float* __restrict__ ext_dst, int to_ext) {
    const int b   = blockIdx.x;
    const int tid = threadIdx.x;   // 256
    __shared__ float red[8];
    __shared__ float s_inv;

    float* __restrict__ dst = to_ext ? ext_dst : g_h;   // device-side resolve
    const float* __restrict__ u = &g_u[b * D];

    float ss = 0.f;
    for (int i = tid; i < D; i += 256) {
        float v = u[i];
        ss = fmaf(v, v, ss);
    }
#pragma unroll
    for (int o = 16; o; o >>= 1) ss += __shfl_down_sync(0xFFFFFFFFu, ss, o);
    if ((tid & 31) == 0) red[tid >> 5] = ss;
    __syncthreads();
    if (tid == 0) {
        float v = 0.f;
#pragma unroll
        for (int w = 0; w < 8; w++) v += red[w];
        s_inv = 1.0f / fmaxf(sqrtf(v), 1e-12f);
    }
    __syncthreads();
    const float inv = s_inv;
    for (int i = tid; i < D; i += 256) {
        dst[b * D + i] = u[i] * inv;
    }
}

// ---------------------------------------------------------------------------
extern "C" void kernel_launch(void* const* d_in, const int* in_sizes, int n_in,
                              void* d_out, int out_size) {
    const float* x  = (const float*)d_in[0];   // (8, 8192)
    const float* M  = (const float*)d_in[1];   // (8192, 8192)
    const float* hs = (const float*)d_in[2];   // (1, 8192) zeros
    float* out = (float*)d_out;                // (8, 8192)

    convert_kernel<<<8192, 256>>>(M);

    // Step 1: pre = 0.5*hs0 + x @ M, then normalize into g_h
    iter_kernel<true><<<128, 512>>>(x, hs);
    norm_kernel<<<8, 256>>>(out, 0);

    // Steps 2..16
    for (int t = 1; t < 16; ++t) {
        iter_kernel<false><<<128, 512>>>(x, hs);
        norm_kernel<<<8, 256>>>(out, t == 15 ? 1 : 0);
    }
}

// round 4
// speedup vs baseline: 1.1290x; 1.1290x over previous
#include <cuda_runtime.h>
#include <cuda_bf16.h>

#define D 8192
#define B 8

// Static device scratch (no runtime allocation allowed).
__device__ __align__(16) __nv_bfloat16 g_Mb[(size_t)D * (size_t)D];  // bf16 M
__device__ __align__(16) float g_u[B * D];    // pre-normalization activations (std layout [b][j])
__device__ __align__(16) float g_hT[D * B];   // normalized state, TRANSPOSED [i][b]

// ---------------------------------------------------------------------------
// Packed f32x2 helpers
// ---------------------------------------------------------------------------
__device__ __forceinline__ unsigned long long pack2u(unsigned lo, unsigned hi) {
    unsigned long long r;
    asm("mov.b64 %0, {%1, %2};" : "=l"(r) : "r"(lo), "r"(hi));
    return r;
}
__device__ __forceinline__ unsigned long long pack2f(float lo, float hi) {
    unsigned long long r;
    asm("mov.b64 %0, {%1, %2};" : "=l"(r) : "f"(lo), "f"(hi));
    return r;
}
__device__ __forceinline__ void unpack2(unsigned long long v, float& lo, float& hi) {
    asm("mov.b64 {%0, %1}, %2;" : "=f"(lo), "=f"(hi) : "l"(v));
}
__device__ __forceinline__ void fma2(unsigned long long& acc, unsigned long long a,
                                     unsigned long long b) {
    asm("fma.rn.f32x2 %0, %1, %2, %0;" : "+l"(acc) : "l"(a), "l"(b));
}

// ---------------------------------------------------------------------------
// One-time fp32 -> bf16 conversion of M
// ---------------------------------------------------------------------------
__global__ void convert_kernel(const float* __restrict__ M) {
    size_t idx    = (size_t)blockIdx.x * blockDim.x + threadIdx.x;
    size_t stride = (size_t)gridDim.x * blockDim.x;
    size_t n4     = (size_t)D * (size_t)D / 4;
    const float4* in4 = reinterpret_cast<const float4*>(M);
    uint2* out4       = reinterpret_cast<uint2*>(g_Mb);
    for (size_t i = idx; i < n4; i += stride) {
        float4 v = in4[i];
        __nv_bfloat162 lo = __floats2bfloat162_rn(v.x, v.y);
        __nv_bfloat162 hi = __floats2bfloat162_rn(v.z, v.w);
        uint2 o;
        o.x = *reinterpret_cast<unsigned*>(&lo);
        o.y = *reinterpret_cast<unsigned*>(&hi);
        out4[i] = o;
    }
}

// ---------------------------------------------------------------------------
// One-time transpose of x (B,D std layout) into g_hT (D,B)
// ---------------------------------------------------------------------------
__global__ void transpose_x_kernel(const float* __restrict__ x) {
    int n = blockIdx.x * blockDim.x + threadIdx.x;   // n = i*8 + b
    if (n < D * B) {
        int i = n >> 3;
        int b = n & 7;
        g_hT[n] = x[b * D + i];
    }
}

// ---------------------------------------------------------------------------
// One step's pre-activation:  u = leaky( 0.5*hs + h @ M ),  h read from g_hT.
//
// Grid: 256 blocks x 512 threads; block owns 32 output columns.
// Warp w (0..15): lane&15 = col-pair cp (cols jb+2cp, jb+2cp+1),
//                 lane>>4 = k-half -> k-slice s = 2w + kh, rows [s*256, +256).
// Accumulators: 4 batch-pairs x 2 cols, packed f32x2 (batch 2k, 2k+1).
// h pairs come pre-packed from the transposed layout (one LDG.128 = 4 pairs).
// ---------------------------------------------------------------------------
template <bool FIRST>
__global__ void __launch_bounds__(512, 2)
iter_kernel(const float* __restrict__ hs_in) {
    const int tid  = threadIdx.x;
    const int lane = tid & 31;
    const int w    = tid >> 5;          // 0..15
    const int cp   = lane & 15;         // col pair within block's 32 cols
    const int kh   = lane >> 4;         // k-half
    const int s    = w * 2 + kh;        // k-slice 0..31, 256 rows each
    const int jb   = blockIdx.x * 32;

    unsigned long long acc[4][2];
#pragma unroll
    for (int p = 0; p < 4; p++) { acc[p][0] = 0ull; acc[p][1] = 0ull; }

    const unsigned* __restrict__ M2 = reinterpret_cast<const unsigned*>(g_Mb);
    const float4*   __restrict__ hT4 = reinterpret_cast<const float4*>(g_hT);

    const int iBeg = s * 256;
#pragma unroll 1
    for (int ii = 0; ii < 256; ii += 2) {
        const int i = iBeg + ii;
        // loads up front (2 M rows, 2 h rows = 4 float4, all independent)
        unsigned mv0 = M2[((size_t)i * D + jb) / 2 + cp];
        unsigned mv1 = M2[((size_t)(i + 1) * D + jb) / 2 + cp];
        float4 h0a = hT4[i * 2 + 0];
        float4 h0b = hT4[i * 2 + 1];
        float4 h1a = hT4[i * 2 + 2];
        float4 h1b = hT4[i * 2 + 3];

        // row i: m dups (bf16 -> f32 is exact 16-bit shift)
        {
            unsigned lo = mv0 << 16, hi = mv0 & 0xFFFF0000u;
            unsigned long long m0 = pack2u(lo, lo);   // (m_j, m_j)
            unsigned long long m1 = pack2u(hi, hi);   // (m_j+1, m_j+1)
            unsigned long long hp0 = pack2f(h0a.x, h0a.y);
            unsigned long long hp1 = pack2f(h0a.z, h0a.w);
            unsigned long long hp2 = pack2f(h0b.x, h0b.y);
            unsigned long long hp3 = pack2f(h0b.z, h0b.w);
            fma2(acc[0][0], hp0, m0); fma2(acc[0][1], hp0, m1);
            fma2(acc[1][0], hp1, m0); fma2(acc[1][1], hp1, m1);
            fma2(acc[2][0], hp2, m0); fma2(acc[2][1], hp2, m1);
            fma2(acc[3][0], hp3, m0); fma2(acc[3][1], hp3, m1);
        }
        // row i+1
        {
            unsigned lo = mv1 << 16, hi = mv1 & 0xFFFF0000u;
            unsigned long long m0 = pack2u(lo, lo);
            unsigned long long m1 = pack2u(hi, hi);
            unsigned long long hp0 = pack2f(h1a.x, h1a.y);
            unsigned long long hp1 = pack2f(h1a.z, h1a.w);
            unsigned long long hp2 = pack2f(h1b.x, h1b.y);
            unsigned long long hp3 = pack2f(h1b.z, h1b.w);
            fma2(acc[0][0], hp0, m0); fma2(acc[0][1], hp0, m1);
            fma2(acc[1][0], hp1, m0); fma2(acc[1][1], hp1, m1);
            fma2(acc[2][0], hp2, m0); fma2(acc[2][1], hp2, m1);
            fma2(acc[3][0], hp3, m0); fma2(acc[3][1], hp3, m1);
        }
    }

    // Unpack to floats: f[b][c], b = batch 0..7, c = col-in-pair 0..1
    float f[8][2];
#pragma unroll
    for (int p = 0; p < 4; p++) {
#pragma unroll
        for (int c = 0; c < 2; c++) {
            float a0, a1;
            unpack2(acc[p][c], a0, a1);
            f[2 * p + 0][c] = a0;
            f[2 * p + 1][c] = a1;
        }
    }
    // Combine the two k-halves sharing a warp (lane l += lane l+16; same cp)
#pragma unroll
    for (int b = 0; b < 8; b++)
#pragma unroll
        for (int c = 0; c < 2; c++)
            f[b][c] += __shfl_down_sync(0xFFFFFFFFu, f[b][c], 16);

    // Cross-warp reduction: smem[(w*8 + b)*33 + col], col = 2*cp + c (0..31)
    __shared__ float smem[16 * 8 * 33];
    if (kh == 0) {
#pragma unroll
        for (int b = 0; b < 8; b++) {
            smem[(w * 8 + b) * 33 + 2 * cp + 0] = f[b][0];
            smem[(w * 8 + b) * 33 + 2 * cp + 1] = f[b][1];
        }
    }
    __syncthreads();

    // Epilogue: threads 0..255 -> 32 cols x 8 batches
    if (tid < 256) {
        const int col = tid & 31;
        const int b   = tid >> 5;
        float ssum = 0.f;
#pragma unroll
        for (int w2 = 0; w2 < 16; w2++) ssum += smem[(w2 * 8 + b) * 33 + col];

        const int j = jb + col;
        const float dec = FIRST ? hs_in[j] : g_hT[j * 8 + b];
        float val = fmaf(0.5f, dec, ssum);
        val = (val >= 0.f) ? val : 0.01f * val;   // leaky_relu
        g_u[b * D + j] = val;
    }
}

// ---------------------------------------------------------------------------
// Row-wise L2 normalize of g_u. Intermediate steps write the TRANSPOSED
// state g_hT[i*8+b]; the final step writes the external output [b*D+i].
// (Destinations resolved in device code; never pass __device__ symbols from
// host — that was the R2 failure.)
// ---------------------------------------------------------------------------
__global__ void norm_kernel(float* __restrict__ ext_dst, int to_ext) {
    const int b   = blockIdx.x;
    const int tid = threadIdx.x;   // 256
    __shared__ float red[8];
    __shared__ float s_inv;

    const float* __restrict__ u = &g_u[b * D];

    float ss = 0.f;
    for (int i = tid; i < D; i += 256) {
        float v = u[i];
        ss = fmaf(v, v, ss);
    }
#pragma unroll
    for (int o = 16; o; o >>= 1) ss += __shfl_down_sync(0xFFFFFFFFu, ss, o);
    if ((tid & 31) == 0) red[tid >> 5] = ss;
    __syncthreads();
    if (tid == 0) {
        float v = 0.f;
#pragma unroll
        for (int w = 0; w < 8; w++) v += red[w];
        s_inv = 1.0f / fmaxf(sqrtf(v), 1e-12f);
    }
    __syncthreads();
    const float inv = s_inv;
    if (to_ext) {
        for (int i = tid; i < D; i += 256) ext_dst[b * D + i] = u[i] * inv;
    } else {
        for (int i = tid; i < D; i += 256) g_hT[i * 8 + b] = u[i] * inv;
    }
}

// ---------------------------------------------------------------------------
extern "C" void kernel_launch(void* const* d_in, const int* in_sizes, int n_in,
                              void* d_out, int out_size) {
    const float* x  = (const float*)d_in[0];   // (8, 8192)
    const float* M  = (const float*)d_in[1];   // (8192, 8192)
    const float* hs = (const float*)d_in[2];   // (1, 8192) zeros
    float* out = (float*)d_out;                // (8, 8192)

    convert_kernel<<<8192, 256>>>(M);
    transpose_x_kernel<<<(D * B + 255) / 256, 256>>>(x);

    // Step 1: pre = 0.5*hs0 + x @ M (x already transposed into g_hT)
    iter_kernel<true><<<256, 512>>>(hs);
    norm_kernel<<<8, 256>>>(out, 0);

    // Steps 2..16
    for (int t = 1; t < 16; ++t) {
        iter_kernel<false><<<256, 512>>>(hs);
        norm_kernel<<<8, 256>>>(out, t == 15 ? 1 : 0);
    }
}

// round 6
// speedup vs baseline: 3.0248x; 2.6792x over previous
#include <cuda_runtime.h>
#include <cuda_bf16.h>
#include <cstdint>

#define D 8192
#define B 8
#define JT 64                       // j-columns per block
#define NWARP 16
#define KSLICE (D / NWARP)          // 512 i per warp
#define NCHUNK (KSLICE / 16)        // 32 chunks of k=16
#define STAGES 4
#define STAGE_BYTES 2048            // 16 i x 64 j bf16
#define SMEM_PIPE (NWARP * STAGES * STAGE_BYTES)   // 131072 B
#define NBLK 128

// Static device scratch (no runtime allocation allowed).
__device__ __align__(16) __nv_bfloat16 g_Mb[(size_t)D * (size_t)D];  // bf16 M
__device__ __align__(16) float    g_u[B * D];              // scaled unnormalized state (fp32, [b][j])
__device__ __align__(16) unsigned g_hb[2][(D / 16) * 64];  // same state, bf16, mma B-fragment order
__device__ __align__(16) float    g_part[2][NBLK][B];      // per-block per-row sum(val^2) partials

// ---------------------------------------------------------------------------
// PTX primitives
// ---------------------------------------------------------------------------
__device__ __forceinline__ void cp_async16(unsigned saddr, const void* gptr) {
    asm volatile("cp.async.cg.shared.global [%0], [%1], 16;" :: "r"(saddr), "l"(gptr));
}
__device__ __forceinline__ void cp_commit() {
    asm volatile("cp.async.commit_group;" ::: "memory");
}
__device__ __forceinline__ void cp_wait3() {
    asm volatile("cp.async.wait_group 3;" ::: "memory");
}
__device__ __forceinline__ void ldmatrix_x4_trans(unsigned& r0, unsigned& r1,
                                                  unsigned& r2, unsigned& r3,
                                                  unsigned addr) {
    asm volatile("ldmatrix.sync.aligned.m8n8.x4.trans.shared.b16 {%0,%1,%2,%3}, [%4];"
                 : "=r"(r0), "=r"(r1), "=r"(r2), "=r"(r3) : "r"(addr) : "memory");
}
__device__ __forceinline__ void mma_bf16(float* d, const unsigned* a, const unsigned* b) {
    asm volatile(
        "mma.sync.aligned.m16n8k16.row.col.f32.bf16.bf16.f32 "
        "{%0,%1,%2,%3},{%4,%5,%6,%7},{%8,%9},{%0,%1,%2,%3};"
        : "+f"(d[0]), "+f"(d[1]), "+f"(d[2]), "+f"(d[3])
        : "r"(a[0]), "r"(a[1]), "r"(a[2]), "r"(a[3]), "r"(b[0]), "r"(b[1]));
}

// ---------------------------------------------------------------------------
// One-time fp32 -> bf16 conversion of M
// ---------------------------------------------------------------------------
__global__ void convert_kernel(const float* __restrict__ M) {
    size_t idx    = (size_t)blockIdx.x * blockDim.x + threadIdx.x;
    size_t stride = (size_t)gridDim.x * blockDim.x;
    size_t n4     = (size_t)D * (size_t)D / 4;
    const float4* in4 = reinterpret_cast<const float4*>(M);
    uint2* out4       = reinterpret_cast<uint2*>(g_Mb);
    for (size_t i = idx; i < n4; i += stride) {
        float4 v = in4[i];
        __nv_bfloat162 lo = __floats2bfloat162_rn(v.x, v.y);
        __nv_bfloat162 hi = __floats2bfloat162_rn(v.z, v.w);
        uint2 o;
        o.x = *reinterpret_cast<unsigned*>(&lo);
        o.y = *reinterpret_cast<unsigned*>(&hi);
        out4[i] = o;
    }
}

// ---------------------------------------------------------------------------
// One-time: x (fp32 [b][i]) -> g_hb[0] in mma B-fragment order (bf16).
// Word(c, L, r) = bf16x2( h[16c + 8r + 2*(L&3)][b=L>>2], h[...+1][b] ),
// stored at index c*64 + L*2 + r.
// ---------------------------------------------------------------------------
__global__ void prep_kernel(const float* __restrict__ x) {
    int wid = blockIdx.x * blockDim.x + threadIdx.x;
    if (wid >= (D / 16) * 64) return;
    int c = wid >> 6;
    int L = (wid >> 1) & 31;
    int r = wid & 1;
    int i0 = c * 16 + r * 8 + 2 * (L & 3);
    int b  = L >> 2;
    __nv_bfloat162 v = __floats2bfloat162_rn(x[b * D + i0], x[b * D + i0 + 1]);
    g_hb[0][wid] = *reinterpret_cast<unsigned*>(&v);
}

// ---------------------------------------------------------------------------
// One step on UNNORMALIZED state (positive homogeneity):
//   u_next = inv_b * leaky( 0.5*u + u @ M )
// inv_b is a per-row positive scalar (lag-one norm estimate): it cancels in
// the final normalize but keeps ||u_b|| in [~0.01, ~1] for BOTH attractors
// (the fixed 2^-12 of R1/R5 underflowed negative-attractor rows to zero).
// ---------------------------------------------------------------------------
template <bool FIRST>
__global__ void __launch_bounds__(512, 1)
iter_kernel(const float* __restrict__ hs_in, int src) {
    extern __shared__ __align__(16) unsigned char smem[];
    __shared__ float arr_ss[16];    // per-warp partials of prev-step row norms
    __shared__ float arr_out[16];   // per-warp partials of this step's row norms
    const int tid = threadIdx.x;
    const int L   = tid & 31;
    const int w   = tid >> 5;
    const int jb  = blockIdx.x * JT;

    const unsigned swarp =
        (unsigned)__cvta_generic_to_shared(smem) + w * (STAGES * STAGE_BYTES);

    const uint2* __restrict__ hb = reinterpret_cast<const uint2*>(g_hb[src]);
    const char*  __restrict__ Mb = reinterpret_cast<const char*>(g_Mb);

    float acc[4][4];
#pragma unroll
    for (int t = 0; t < 4; t++)
#pragma unroll
        for (int q = 0; q < 4; q++) acc[t][q] = 0.f;

    const int i_base = w * KSLICE;
    const int cprow  = L >> 3;
    const int cbcol  = L & 7;
    const int lm_ir  = ((L >> 4) & 1) * 8 + (L & 7);
    const int lm_cbh = (L >> 3) & 1;

#define ISSUE(c)                                                              \
    {                                                                         \
        const int _c = (c);                                                   \
        unsigned sb = swarp + (_c & (STAGES - 1)) * STAGE_BYTES;              \
        const char* gb = Mb + ((size_t)(i_base + _c * 16) * D + jb) * 2;      \
        _Pragma("unroll")                                                     \
        for (int v = 0; v < 4; v++) {                                         \
            int ir  = v * 4 + cprow;                                          \
            int scc = cbcol ^ (ir & 7);                                       \
            cp_async16(sb + ir * 128 + scc * 16,                              \
                       gb + (size_t)ir * (D * 2) + cbcol * 16);               \
        }                                                                     \
    }

    ISSUE(0); cp_commit();
    ISSUE(1); cp_commit();
    ISSUE(2); cp_commit();

#pragma unroll 1
    for (int c = 0; c < NCHUNK; c++) {
        if (c + 3 < NCHUNK) ISSUE(c + 3);
        cp_commit();
        cp_wait3();
        __syncwarp();

        const unsigned sb = swarp + (c & (STAGES - 1)) * STAGE_BYTES;
        uint2 bw = hb[(i_base / 16 + c) * 32 + L];
        unsigned br[2] = {bw.x, bw.y};

#pragma unroll
        for (int jt = 0; jt < 4; jt++) {
            unsigned a[4];
            unsigned cc = (unsigned)((jt * 2 + lm_cbh) ^ (lm_ir & 7));
            ldmatrix_x4_trans(a[0], a[1], a[2], a[3], sb + lm_ir * 128 + cc * 16);
            mma_bf16(acc[jt], a, br);
        }
        __syncwarp();
    }
#undef ISSUE

    // ---- gather prev-step row norms (deterministic tree, no atomics) ----
    // thread tid: b = tid>>6 (warp-uniform), sums 2 of the 128 block partials
    float ssp = 0.f;
    if (!FIRST) {
        const int k  = tid & 63;
        const int bb = tid >> 6;
        ssp = g_part[src ^ 1][2 * k][bb] + g_part[src ^ 1][2 * k + 1][bb];
#pragma unroll
        for (int o = 16; o; o >>= 1) ssp += __shfl_down_sync(0xFFFFFFFFu, ssp, o);
    }

    // ---- split-K reduction (reuse pipeline smem) ----
    __syncthreads();
    float* red = reinterpret_cast<float*>(smem);
    {
        float* rw = red + w * 512;   // [b*64 + j_local]
#pragma unroll
        for (int jt = 0; jt < 4; jt++) {
            int j_l = jt * 16 + (L >> 2);
            int b0  = 2 * (L & 3);
            rw[(b0 + 0) * 64 + j_l]     = acc[jt][0];
            rw[(b0 + 1) * 64 + j_l]     = acc[jt][1];
            rw[(b0 + 0) * 64 + j_l + 8] = acc[jt][2];
            rw[(b0 + 1) * 64 + j_l + 8] = acc[jt][3];
        }
    }
    if (!FIRST && L == 0) arr_ss[w] = ssp;
    __syncthreads();

    // ---- epilogue: 512 threads = 64 j x 8 b ----
    {
        const int j_l = tid & 63;
        const int b   = tid >> 6;
        float s = 0.f;
#pragma unroll
        for (int ww = 0; ww < NWARP; ww++) s += red[ww * 512 + b * 64 + j_l];

        float inv;
        if (FIRST) {
            inv = 0.000244140625f;   // 2^-12; adaptive from step 2 on
        } else {
            float sstot = arr_ss[2 * b] + arr_ss[2 * b + 1];
            inv = 0.000244140625f * rsqrtf(fmaxf(sstot, 1e-30f));
        }

        const int j = jb + j_l;
        const float dec = FIRST ? hs_in[j] : g_u[b * D + j];
        float val = fmaf(0.5f, dec, s);
        val = (val >= 0.f) ? val : 0.01f * val;   // leaky_relu
        val *= inv;                                // per-row positive scale
        g_u[b * D + j] = val;

        // scatter bf16 into next step's B-fragment buffer
        const int cch  = j >> 4;
        const int r    = (j >> 3) & 1;
        const int cls  = (j >> 1) & 3;
        const int Ld   = b * 4 + cls;
        const int word = cch * 64 + Ld * 2 + r;
        reinterpret_cast<__nv_bfloat16*>(g_hb[src ^ 1])[word * 2 + (j & 1)] =
            __float2bfloat16(val);

        // this step's per-row sum(val^2): warp-reduce (b is warp-uniform)
        float v2 = val * val;
#pragma unroll
        for (int o = 16; o; o >>= 1) v2 += __shfl_down_sync(0xFFFFFFFFu, v2, o);
        if (L == 0) arr_out[w] = v2;
    }
    __syncthreads();
    if (tid < B)   // 8 plain stores per block, deterministic
        g_part[src][blockIdx.x][tid] = arr_out[2 * tid] + arr_out[2 * tid + 1];
}

// ---------------------------------------------------------------------------
// Final L2 normalize of g_u rows into the external output.
// (g_u resolved in device code; never pass __device__ symbols from host.)
// ---------------------------------------------------------------------------
__global__ void norm_kernel(float* __restrict__ out) {
    const int b   = blockIdx.x;
    const int tid = threadIdx.x;   // 256
    __shared__ float red[8];
    __shared__ float s_inv;

    const float* __restrict__ u = &g_u[b * D];

    float ss = 0.f;
    for (int i = tid; i < D; i += 256) {
        float v = u[i];
        ss = fmaf(v, v, ss);
    }
#pragma unroll
    for (int o = 16; o; o >>= 1) ss += __shfl_down_sync(0xFFFFFFFFu, ss, o);
    if ((tid & 31) == 0) red[tid >> 5] = ss;
    __syncthreads();
    if (tid == 0) {
        float v = 0.f;
#pragma unroll
        for (int w = 0; w < 8; w++) v += red[w];
        s_inv = 1.0f / fmaxf(sqrtf(v), 1e-12f);
    }
    __syncthreads();
    const float inv = s_inv;
    for (int i = tid; i < D; i += 256) out[b * D + i] = u[i] * inv;
}

// ---------------------------------------------------------------------------
extern "C" void kernel_launch(void* const* d_in, const int* in_sizes, int n_in,
                              void* d_out, int out_size) {
    const float* x  = (const float*)d_in[0];   // (8, 8192)
    const float* M  = (const float*)d_in[1];   // (8192, 8192)
    const float* hs = (const float*)d_in[2];   // (1, 8192) zeros
    float* out = (float*)d_out;                // (8, 8192)

    cudaFuncSetAttribute((const void*)&iter_kernel<true>,
                         cudaFuncAttributeMaxDynamicSharedMemorySize, SMEM_PIPE);
    cudaFuncSetAttribute((const void*)&iter_kernel<false>,
                         cudaFuncAttributeMaxDynamicSharedMemorySize, SMEM_PIPE);

    convert_kernel<<<8192, 256>>>(M);
    prep_kernel<<<(D / 16 * 64 + 255) / 256, 256>>>(x);   // x -> g_hb[0]

    // 16 homogeneous iterations; src ping-pongs 0,1,0,...
    iter_kernel<true><<<NBLK, 512, SMEM_PIPE>>>(hs, 0);
    for (int t = 1; t < 16; ++t)
        iter_kernel<false><<<NBLK, 512, SMEM_PIPE>>>(hs, t & 1);

    // One final normalize (direction of u_16 == hs_16)
    norm_kernel<<<8, 256>>>(out);
}